// round 4
// baseline (speedup 1.0000x reference)
#include <cuda_runtime.h>
#include <cstdint>

#define G 32           // groups
#define CG 2           // channels per group (C=64)
#define MAXB 1024      // max supported batch size for scratch sizing
#define EPSF 1e-5f
#define U 8            // points per warp-iteration in stats

// Scratch (device globals: allocation-free per harness rules).
// Zero-initialized at load; the fused finalize (last stats block) self-resets
// everything it consumed, so every graph replay sees zeroed accumulators.
__device__ float  g_s1[MAXB * G];
__device__ float  g_s2[MAXB * G];
__device__ float  g_cnt[MAXB];
__device__ unsigned int g_done = 0;
__device__ __align__(16) float2 g_mi[MAXB * G];   // (mean, inv) per (b, g)

// packed helpers (f32x2 — PTX-only on sm_103a)
__device__ __forceinline__ unsigned long long pack_f32x2(float lo, float hi) {
    unsigned long long r;
    asm("mov.b64 %0, {%1, %2};" : "=l"(r) : "f"(lo), "f"(hi));
    return r;
}
__device__ __forceinline__ void unpack_f32x2(unsigned long long v, float& lo, float& hi) {
    asm("mov.b64 {%0, %1}, %2;" : "=f"(lo), "=f"(hi) : "l"(v));
}
__device__ __forceinline__ void acc_if_eq(unsigned long long& acc, int b, int bb,
                                          unsigned long long vp) {
    asm("{\n\t"
        ".reg .pred p;\n\t"
        "setp.eq.s32 p, %1, %2;\n\t"
        "@p add.rn.f32x2 %0, %0, %3;\n\t"
        "}" : "+l"(acc) : "r"(b), "r"(bb), "l"(vp));
}

// ---------------------------------------------------------------------------
// Kernel 1: stats (+ fused finalize in the last block to finish).
// Warp-per-point, lane L owns group L (channels 2L,2L+1).
// Fast path (B<=8): batch 8 LDG.64 up front (MLP=8), packed f32x2 binning.
// ---------------------------------------------------------------------------
__global__ void __launch_bounds__(256, 5) stats_kernel(const float* __restrict__ feat,
                                                       const int* __restrict__ bidx,
                                                       int N, const int* __restrict__ Bp) {
    const int B = *Bp;
    const int lane   = threadIdx.x & 31;
    const int gwarp  = (blockIdx.x * blockDim.x + threadIdx.x) >> 5;
    const int nwarps = (gridDim.x * blockDim.x) >> 5;

    if (B <= 8) {
        unsigned long long acc[8];   // packed (sum, sumsq) per bin
#pragma unroll
        for (int bb = 0; bb < 8; bb++) acc[bb] = 0ULL;
        float cnt = 0.0f;            // lane L accumulates count of bin L (L<8)

        int base = gwarp * U;
        const int stride = nwarps * U;
        for (; base + (U - 1) < N; base += stride) {
            // ---- phase 1: batch all loads (front-batched LDGs -> high MLP)
            const int myb = (lane < U) ? __ldg(bidx + base + lane) : 0;
            float2 xb[U];
#pragma unroll
            for (int j = 0; j < U; j++)
                xb[j] = __ldg(reinterpret_cast<const float2*>(
                              feat + (size_t)(base + j) * 64) + lane);
            // ---- phase 2: bin (packed f32x2 predicated adds)
#pragma unroll
            for (int j = 0; j < U; j++) {
                const int b = __shfl_sync(0xFFFFFFFFu, myb, j);
                const float v  = xb[j].x + xb[j].y;
                const float v2 = fmaf(xb[j].x, xb[j].x, xb[j].y * xb[j].y);
                const unsigned long long vp = pack_f32x2(v, v2);
#pragma unroll
                for (int bb = 0; bb < 8; bb++) acc_if_eq(acc[bb], b, bb, vp);
                if (lane == b) cnt += 1.0f;
            }
        }
        // tail
        for (; base < N; base++) {
            const int b = __ldg(bidx + base);
            const float2 x = __ldg(reinterpret_cast<const float2*>(
                                   feat + (size_t)base * 64) + lane);
            const unsigned long long vp =
                pack_f32x2(x.x + x.y, fmaf(x.x, x.x, x.y * x.y));
#pragma unroll
            for (int bb = 0; bb < 8; bb++) acc_if_eq(acc[bb], b, bb, vp);
            if (lane == b) cnt += 1.0f;
        }

        // Block-level reduction in shared, then <=520 global atomics per block
        __shared__ float sh1[8 * G];
        __shared__ float sh2[8 * G];
        __shared__ float shc[8];
        for (int i = threadIdx.x; i < 8 * G; i += blockDim.x) { sh1[i] = 0.0f; sh2[i] = 0.0f; }
        if (threadIdx.x < 8) shc[threadIdx.x] = 0.0f;
        __syncthreads();
#pragma unroll
        for (int bb = 0; bb < 8; bb++) {
            float a1, a2;
            unpack_f32x2(acc[bb], a1, a2);
            atomicAdd(&sh1[bb * G + lane], a1);
            atomicAdd(&sh2[bb * G + lane], a2);
        }
        if (lane < 8 && cnt != 0.0f) atomicAdd(&shc[lane], cnt);
        __syncthreads();
        const int i = threadIdx.x;            // exactly 256 = 8*G entries
        if (sh1[i] != 0.0f || sh2[i] != 0.0f) {
            atomicAdd(&g_s1[i], sh1[i]);
            atomicAdd(&g_s2[i], sh2[i]);
        }
        if (i < 8 && shc[i] != 0.0f) atomicAdd(&g_cnt[i], shc[i]);
    } else {
        // Generic fallback: per-point global atomics (rare path)
        for (int p = gwarp; p < N; p += nwarps) {
            const int b = __ldg(bidx + p);
            if (b < 0 || b >= MAXB) continue;
            const float2 x = __ldg(reinterpret_cast<const float2*>(
                                   feat + (size_t)p * 64) + lane);
            atomicAdd(&g_s1[b * G + lane], x.x + x.y);
            atomicAdd(&g_s2[b * G + lane], fmaf(x.x, x.x, x.y * x.y));
            if (lane == 0) atomicAdd(&g_cnt[b], 1.0f);
        }
    }

    // ---- fused finalize: the last block to finish computes (mean, inv) and
    // resets all accumulators + the ticket for the next graph replay.
    __shared__ unsigned int s_ticket;
    __threadfence();
    if (threadIdx.x == 0) s_ticket = atomicAdd(&g_done, 1u);
    __syncthreads();
    if (s_ticket == (unsigned)(gridDim.x - 1)) {
        __threadfence();
        int BB = B < 1 ? 1 : (B > MAXB ? MAXB : B);
        for (int i = threadIdx.x; i < BB * G; i += blockDim.x) {
            const int b = i >> 5;
            const float c    = fmaxf(g_cnt[b] * (float)CG, 1.0f);
            const float mean = g_s1[i] / c;
            const float var  = g_s2[i] / c - mean * mean;
            const float inv  = rsqrtf(var + EPSF);
            g_mi[i] = make_float2(mean, inv);
            g_s1[i] = 0.0f;
            g_s2[i] = 0.0f;
        }
        __syncthreads();
        for (int b = threadIdx.x; b < BB; b += blockDim.x) g_cnt[b] = 0.0f;
        if (threadIdx.x == 0) g_done = 0;
    }
}

// ---------------------------------------------------------------------------
// Kernel 2: normalize. Half-warp per point; lane handles 4 channels (2 groups)
// via LDG.128 feat + LDG.128 (mean,inv)x2 + STG.128.
//   out = (x - mean) * inv * w + bias
// ---------------------------------------------------------------------------
__global__ void __launch_bounds__(256) normalize_kernel(const float* __restrict__ feat,
                                                        const int* __restrict__ bidx,
                                                        const float* __restrict__ w,
                                                        const float* __restrict__ bias,
                                                        float* __restrict__ out, int N) {
    const int lane   = threadIdx.x & 31;
    const int half   = lane >> 4;          // 0 or 1: which point of the pair
    const int sub    = lane & 15;          // 16 lanes x 4 channels = 64
    const int gwarp  = (blockIdx.x * blockDim.x + threadIdx.x) >> 5;
    const int nwarps = (gridDim.x * blockDim.x) >> 5;

    // Per-lane channel constants (4 channels per lane), loaded once.
    const float4 wv = __ldg(reinterpret_cast<const float4*>(w) + sub);
    const float4 bv = __ldg(reinterpret_cast<const float4*>(bias) + sub);

    int base = gwarp * 8;
    const int stride = nwarps * 8;
    for (; base + 7 < N; base += stride) {
#pragma unroll
        for (int j = 0; j < 4; j++) {
            const int q = base + 2 * j + half;
            const int b = __ldg(bidx + q);
            // two consecutive (mean, inv) pairs for groups 2*sub, 2*sub+1
            const float4 mi = __ldg(reinterpret_cast<const float4*>(
                                    g_mi + b * G) + sub);
            const float4 x = __ldg(reinterpret_cast<const float4*>(
                                   feat + (size_t)q * 64) + sub);
            float4 y;
            y.x = fmaf(x.x - mi.x, mi.y * wv.x, bv.x);
            y.y = fmaf(x.y - mi.x, mi.y * wv.y, bv.y);
            y.z = fmaf(x.z - mi.z, mi.w * wv.z, bv.z);
            y.w = fmaf(x.w - mi.z, mi.w * wv.w, bv.w);
            reinterpret_cast<float4*>(out + (size_t)q * 64)[sub] = y;
        }
    }
    // tail: remaining points of this warp's final chunk
    for (int q = base + half; q < N; q += 2) {
        const int b = __ldg(bidx + q);
        const float4 mi = __ldg(reinterpret_cast<const float4*>(g_mi + b * G) + sub);
        const float4 x = __ldg(reinterpret_cast<const float4*>(
                               feat + (size_t)q * 64) + sub);
        float4 y;
        y.x = fmaf(x.x - mi.x, mi.y * wv.x, bv.x);
        y.y = fmaf(x.y - mi.x, mi.y * wv.y, bv.y);
        y.z = fmaf(x.z - mi.z, mi.w * wv.z, bv.z);
        y.w = fmaf(x.w - mi.z, mi.w * wv.w, bv.w);
        reinterpret_cast<float4*>(out + (size_t)q * 64)[sub] = y;
    }
}

// ---------------------------------------------------------------------------
// kernel_launch
// inputs: 0=features [N*64] f32, 1=weight [64] f32, 2=bias [64] f32,
//         3=batch_idx [N] i32, 4=batch_size [1] i32 (device scalar)
// ---------------------------------------------------------------------------
extern "C" void kernel_launch(void* const* d_in, const int* in_sizes, int n_in,
                              void* d_out, int out_size) {
    const float* feat = (const float*)d_in[0];
    const float* w    = (const float*)d_in[1];
    const float* bias = (const float*)d_in[2];
    const int*   bidx = (const int*)d_in[3];
    const int*   Bp   = (const int*)d_in[4];
    float* out = (float*)d_out;

    const int N = in_sizes[3];           // batch_idx element count == N points

    const int threads = 256;
    int big_blocks = (N + 31) / 32;
    if (big_blocks > 1184) big_blocks = 1184;   // 148 SMs * 8 blocks
    if (big_blocks < 1) big_blocks = 1;

    stats_kernel<<<big_blocks, threads>>>(feat, bidx, N, Bp);
    normalize_kernel<<<big_blocks, threads>>>(feat, bidx, w, bias, out, N);
}

// round 5
// speedup vs baseline: 1.1487x; 1.1487x over previous
#include <cuda_runtime.h>
#include <cstdint>

#define G 32           // groups
#define CG 2           // channels per group (C=64)
#define MAXB 1024      // max supported batch size for scratch sizing
#define EPSF 1e-5f
#define U 8            // points per warp-iteration

// Scratch (device globals: allocation-free per harness rules).
// Zero-initialized at load; the fused finalize (last stats block) self-resets
// everything it consumed, so every graph replay sees zeroed accumulators.
__device__ float  g_s1[MAXB * G];
__device__ float  g_s2[MAXB * G];
__device__ float  g_cnt[MAXB];
__device__ unsigned int g_done = 0;
__device__ __align__(16) float2 g_mi[MAXB * G];   // (mean, inv) per (b, g)

// packed helpers (f32x2 — PTX-only on sm_103a)
__device__ __forceinline__ unsigned long long pack_f32x2(float lo, float hi) {
    unsigned long long r;
    asm("mov.b64 %0, {%1, %2};" : "=l"(r) : "f"(lo), "f"(hi));
    return r;
}
__device__ __forceinline__ void unpack_f32x2(unsigned long long v, float& lo, float& hi) {
    asm("mov.b64 {%0, %1}, %2;" : "=f"(lo), "=f"(hi) : "l"(v));
}
__device__ __forceinline__ void acc_if_eq(unsigned long long& acc, int b, int bb,
                                          unsigned long long vp) {
    asm("{\n\t"
        ".reg .pred p;\n\t"
        "setp.eq.s32 p, %1, %2;\n\t"
        "@p add.rn.f32x2 %0, %0, %3;\n\t"
        "}" : "+l"(acc) : "r"(b), "r"(bb), "l"(vp));
}

// ---------------------------------------------------------------------------
// Kernel 1: stats (+ fused finalize in the last block to finish).
// Warp-per-point, lane L owns group L (channels 2L,2L+1).
// Fast path (B<=8): batch 8 LDG.64 up front (MLP=8), packed f32x2 binning.
// ---------------------------------------------------------------------------
__global__ void __launch_bounds__(256, 5) stats_kernel(const float* __restrict__ feat,
                                                       const int* __restrict__ bidx,
                                                       int N, const int* __restrict__ Bp) {
    const int B = *Bp;
    const int lane   = threadIdx.x & 31;
    const int gwarp  = (blockIdx.x * blockDim.x + threadIdx.x) >> 5;
    const int nwarps = (gridDim.x * blockDim.x) >> 5;

    if (B <= 8) {
        unsigned long long acc[8];   // packed (sum, sumsq) per bin
#pragma unroll
        for (int bb = 0; bb < 8; bb++) acc[bb] = 0ULL;
        float cnt = 0.0f;            // lane L accumulates count of bin L (L<8)

        int base = gwarp * U;
        const int stride = nwarps * U;
        for (; base + (U - 1) < N; base += stride) {
            // ---- phase 1: batch all loads (front-batched LDGs -> high MLP)
            const int myb = (lane < U) ? __ldg(bidx + base + lane) : 0;
            float2 xb[U];
#pragma unroll
            for (int j = 0; j < U; j++)
                xb[j] = __ldg(reinterpret_cast<const float2*>(
                              feat + (size_t)(base + j) * 64) + lane);
            // ---- phase 2: bin (packed f32x2 predicated adds)
#pragma unroll
            for (int j = 0; j < U; j++) {
                const int b = __shfl_sync(0xFFFFFFFFu, myb, j);
                const float v  = xb[j].x + xb[j].y;
                const float v2 = fmaf(xb[j].x, xb[j].x, xb[j].y * xb[j].y);
                const unsigned long long vp = pack_f32x2(v, v2);
#pragma unroll
                for (int bb = 0; bb < 8; bb++) acc_if_eq(acc[bb], b, bb, vp);
                if (lane == b) cnt += 1.0f;
            }
        }
        // tail
        for (; base < N; base++) {
            const int b = __ldg(bidx + base);
            const float2 x = __ldg(reinterpret_cast<const float2*>(
                                   feat + (size_t)base * 64) + lane);
            const unsigned long long vp =
                pack_f32x2(x.x + x.y, fmaf(x.x, x.x, x.y * x.y));
#pragma unroll
            for (int bb = 0; bb < 8; bb++) acc_if_eq(acc[bb], b, bb, vp);
            if (lane == b) cnt += 1.0f;
        }

        // Block-level reduction in shared, then <=520 global atomics per block
        __shared__ float sh1[8 * G];
        __shared__ float sh2[8 * G];
        __shared__ float shc[8];
        for (int i = threadIdx.x; i < 8 * G; i += blockDim.x) { sh1[i] = 0.0f; sh2[i] = 0.0f; }
        if (threadIdx.x < 8) shc[threadIdx.x] = 0.0f;
        __syncthreads();
#pragma unroll
        for (int bb = 0; bb < 8; bb++) {
            float a1, a2;
            unpack_f32x2(acc[bb], a1, a2);
            atomicAdd(&sh1[bb * G + lane], a1);
            atomicAdd(&sh2[bb * G + lane], a2);
        }
        if (lane < 8 && cnt != 0.0f) atomicAdd(&shc[lane], cnt);
        __syncthreads();
        const int i = threadIdx.x;            // exactly 256 = 8*G entries
        if (sh1[i] != 0.0f || sh2[i] != 0.0f) {
            atomicAdd(&g_s1[i], sh1[i]);
            atomicAdd(&g_s2[i], sh2[i]);
        }
        if (i < 8 && shc[i] != 0.0f) atomicAdd(&g_cnt[i], shc[i]);
    } else {
        // Generic fallback: per-point global atomics (rare path)
        for (int p = gwarp; p < N; p += nwarps) {
            const int b = __ldg(bidx + p);
            if (b < 0 || b >= MAXB) continue;
            const float2 x = __ldg(reinterpret_cast<const float2*>(
                                   feat + (size_t)p * 64) + lane);
            atomicAdd(&g_s1[b * G + lane], x.x + x.y);
            atomicAdd(&g_s2[b * G + lane], fmaf(x.x, x.x, x.y * x.y));
            if (lane == 0) atomicAdd(&g_cnt[b], 1.0f);
        }
    }

    // ---- fused finalize: the last block to finish computes (mean, inv) and
    // resets all accumulators + the ticket for the next graph replay.
    __shared__ unsigned int s_ticket;
    __threadfence();
    if (threadIdx.x == 0) s_ticket = atomicAdd(&g_done, 1u);
    __syncthreads();
    if (s_ticket == (unsigned)(gridDim.x - 1)) {
        __threadfence();
        int BB = B < 1 ? 1 : (B > MAXB ? MAXB : B);
        for (int i = threadIdx.x; i < BB * G; i += blockDim.x) {
            const int b = i >> 5;
            const float c    = fmaxf(g_cnt[b] * (float)CG, 1.0f);
            const float mean = g_s1[i] / c;
            const float var  = g_s2[i] / c - mean * mean;
            const float inv  = rsqrtf(var + EPSF);
            g_mi[i] = make_float2(mean, inv);
            g_s1[i] = 0.0f;
            g_s2[i] = 0.0f;
        }
        __syncthreads();
        for (int b = threadIdx.x; b < BB; b += blockDim.x) g_cnt[b] = 0.0f;
        if (threadIdx.x == 0) g_done = 0;
    }
}

// ---------------------------------------------------------------------------
// Kernel 2: normalize. Warp-per-point, lane L handles channels 2L,2L+1.
// Front-batched like stats: 1 lane-strided bidx LDG + 8 feat LDG.64 issued
// before the 8 dependent table LDG.64s; then compute + 8 STG.64.
//   out = (x - mean) * inv * w + bias
// ---------------------------------------------------------------------------
__global__ void __launch_bounds__(256) normalize_kernel(const float* __restrict__ feat,
                                                        const int* __restrict__ bidx,
                                                        const float* __restrict__ w,
                                                        const float* __restrict__ bias,
                                                        float* __restrict__ out, int N) {
    const int lane   = threadIdx.x & 31;
    const int gwarp  = (blockIdx.x * blockDim.x + threadIdx.x) >> 5;
    const int nwarps = (gridDim.x * blockDim.x) >> 5;

    // Per-lane channel constants (2 channels per lane), loaded once.
    const float2 wv = __ldg(reinterpret_cast<const float2*>(w) + lane);
    const float2 bv = __ldg(reinterpret_cast<const float2*>(bias) + lane);

    int base = gwarp * U;
    const int stride = nwarps * U;
    for (; base + (U - 1) < N; base += stride) {
        // phase 1: the index load, then 8 independent feature loads fill the
        // shfl/table latency
        const int myb = (lane < U) ? __ldg(bidx + base + lane) : 0;
        float2 xb[U];
#pragma unroll
        for (int j = 0; j < U; j++)
            xb[j] = __ldg(reinterpret_cast<const float2*>(
                          feat + (size_t)(base + j) * 64) + lane);
        // phase 2: dependent table loads, batched (L1-resident, 2KB table)
        float2 mi[U];
#pragma unroll
        for (int j = 0; j < U; j++) {
            const int b = __shfl_sync(0xFFFFFFFFu, myb, j);
            mi[j] = __ldg(&g_mi[b * G + lane]);
        }
        // phase 3: compute + store
#pragma unroll
        for (int j = 0; j < U; j++) {
            float2 y;
            y.x = fmaf(xb[j].x - mi[j].x, mi[j].y * wv.x, bv.x);
            y.y = fmaf(xb[j].y - mi[j].x, mi[j].y * wv.y, bv.y);
            reinterpret_cast<float2*>(out + (size_t)(base + j) * 64)[lane] = y;
        }
    }
    // tail
    for (; base < N; base++) {
        const int b = __ldg(bidx + base);
        const float2 mi = __ldg(&g_mi[b * G + lane]);
        const float2 x = __ldg(reinterpret_cast<const float2*>(
                               feat + (size_t)base * 64) + lane);
        float2 y;
        y.x = fmaf(x.x - mi.x, mi.y * wv.x, bv.x);
        y.y = fmaf(x.y - mi.x, mi.y * wv.y, bv.y);
        reinterpret_cast<float2*>(out + (size_t)base * 64)[lane] = y;
    }
}

// ---------------------------------------------------------------------------
// kernel_launch
// inputs: 0=features [N*64] f32, 1=weight [64] f32, 2=bias [64] f32,
//         3=batch_idx [N] i32, 4=batch_size [1] i32 (device scalar)
// ---------------------------------------------------------------------------
extern "C" void kernel_launch(void* const* d_in, const int* in_sizes, int n_in,
                              void* d_out, int out_size) {
    const float* feat = (const float*)d_in[0];
    const float* w    = (const float*)d_in[1];
    const float* bias = (const float*)d_in[2];
    const int*   bidx = (const int*)d_in[3];
    const int*   Bp   = (const int*)d_in[4];
    float* out = (float*)d_out;

    const int N = in_sizes[3];           // batch_idx element count == N points

    const int threads = 256;
    int big_blocks = (N + 31) / 32;
    if (big_blocks > 1184) big_blocks = 1184;   // 148 SMs * 8 blocks
    if (big_blocks < 1) big_blocks = 1;

    stats_kernel<<<big_blocks, threads>>>(feat, bidx, N, Bp);
    normalize_kernel<<<big_blocks, threads>>>(feat, bidx, w, bias, out, N);
}